// round 3
// baseline (speedup 1.0000x reference)
#include <cuda_runtime.h>
#include <cuda_bf16.h>
#include <math.h>

// Attention path collapses (softmax rows sum to 1; T,S fully contracted):
//   y = 1024 * (h_pred @ Wv + bv)
// Only Wv/Wo projection + gate MLP + mixer MLP survive.
//
// R2: latency-bound fix #2 — 1024 threads/CTA (8-way k-slice, 8 warps/SMSP),
// full weight-slice register preload (MLP=16), register-carried out/h_corr.

#define HID 128
#define ROWS 8
#define SLICES 8
#define KS (HID / SLICES)        // 16 k-values per slice
#define NNODES 1024
#define NTHREADS (HID * SLICES)  // 1024

typedef unsigned long long u64;

__device__ __forceinline__ u64 fma2(u64 a, u64 b, u64 c) {
    u64 d;
    asm("fma.rn.f32x2 %0, %1, %2, %3;" : "=l"(d) : "l"(a), "l"(b), "l"(c));
    return d;
}

// Partial GEMM over this slice's k-range; weights preloaded to registers first.
__device__ __forceinline__ void gemm_slice(const float* __restrict__ W,
                                           const float (*__restrict__ sT)[ROWS],
                                           int c, int k0, u64 acc[4]) {
    float w[KS];
#pragma unroll
    for (int i = 0; i < KS; i++) w[i] = W[(k0 + i) * HID + c];
#pragma unroll
    for (int i = 0; i < KS; i++) {
        u64 ww;
        asm("mov.b64 %0, {%1, %1};" : "=l"(ww) : "f"(w[i]));
        const u64* a = (const u64*)(&sT[k0 + i][0]);  // 8 rows = 4x float2
        acc[0] = fma2(a[0], ww, acc[0]);
        acc[1] = fma2(a[1], ww, acc[1]);
        acc[2] = fma2(a[2], ww, acc[2]);
        acc[3] = fma2(a[3], ww, acc[3]);
    }
}

extern "C" __global__ void __launch_bounds__(NTHREADS, 1)
temporal_attn_fused(const float* __restrict__ h_prev,
                    const float* __restrict__ h_pred,
                    const float* __restrict__ Wv, const float* __restrict__ bv,
                    const float* __restrict__ Wo, const float* __restrict__ bo,
                    const float* __restrict__ gW1, const float* __restrict__ gb1,
                    const float* __restrict__ gW2, const float* __restrict__ gb2,
                    const float* __restrict__ mW1, const float* __restrict__ mb1,
                    const float* __restrict__ mW2, const float* __restrict__ mb2,
                    float* __restrict__ out) {
    __shared__ float hpT[HID][ROWS];           // 4KB  h_pred tile, [k][r]
    __shared__ float hvT[HID][ROWS];           // 4KB  h_prev tile
    __shared__ float tmpT[HID][ROWS];          // 4KB  v / g1 / m1 scratch
    __shared__ float hcT[HID][ROWS];           // 4KB  h_corr
    __shared__ float part[SLICES][HID][ROWS];  // 32KB per-slice partials

    const int tid = threadIdx.x;
    const int c = tid & (HID - 1);   // output column for GEMM phase
    const int s = tid >> 7;          // k-slice 0..7
    const int k0 = s * KS;
    const int r0 = blockIdx.x * ROWS;

    float* hvF  = (float*)hvT;
    float* tmpF = (float*)tmpT;
    float* hcF  = (float*)hcT;
    float* pF   = (float*)part;      // pF[s*1024 + p], p = c*8 + r

    // Stage inputs transposed (coalesced global reads; 1 elem/thread/tensor).
    {
        int r = tid >> 7, cc = tid & (HID - 1);
        hpT[cc][r] = h_pred[(r0 + r) * HID + cc];
        hvT[cc][r] = h_prev[(r0 + r) * HID + cc];
    }
    __syncthreads();

    u64 acc[4];
    u64* pdst = (u64*)&part[s][c][0];
    const int p = tid;               // element owned in every reduce phase
    const int bidx = p >> 3;         // bias index (column) for element p

#define GEMM_ZERO()  { acc[0] = acc[1] = acc[2] = acc[3] = 0ULL; }
#define GEMM_STORE() { pdst[0] = acc[0]; pdst[1] = acc[1]; pdst[2] = acc[2]; pdst[3] = acc[3]; }
#define REDUCE(x)    float x = pF[p] + pF[1024 + p] + pF[2048 + p] + pF[3072 + p] \
                             + pF[4096 + p] + pF[5120 + p] + pF[6144 + p] + pF[7168 + p]

    float outv, hcv;  // register-carried out / h_corr for element p

    // ---- Stage 1: v = h_pred @ Wv + bv -> tmpT ----
    GEMM_ZERO();
    gemm_slice(Wv, hpT, c, k0, acc);
    GEMM_STORE();
    __syncthreads();
    { REDUCE(v); tmpF[p] = v + bv[bidx]; }
    __syncthreads();

    // ---- Stage 2: out = 1024*(v @ Wo) + bo -> register outv ----
    GEMM_ZERO();
    gemm_slice(Wo, tmpT, c, k0, acc);
    GEMM_STORE();
    __syncthreads();
    { REDUCE(v); outv = (float)NNODES * v + bo[bidx]; }
    __syncthreads();

    // ---- Stage 3: g1 = silu(h_pred@gW1_top + h_prev@gW1_bot + gb1) -> tmpT ----
    GEMM_ZERO();
    gemm_slice(gW1, hpT, c, k0, acc);
    gemm_slice(gW1 + HID * HID, hvT, c, k0, acc);
    GEMM_STORE();
    __syncthreads();
    { REDUCE(x); x += gb1[bidx]; tmpF[p] = x / (1.0f + __expf(-x)); }
    __syncthreads();

    // ---- Stage 4: gate = sigmoid(g1@gW2 + gb2); h_corr = h_prev + gate*out ----
    GEMM_ZERO();
    gemm_slice(gW2, tmpT, c, k0, acc);
    GEMM_STORE();
    __syncthreads();
    {
        REDUCE(x); x += gb2[bidx];
        float g = 1.0f / (1.0f + __expf(-x));
        hcv = hvF[p] + g * outv;
        hcF[p] = hcv;
    }
    __syncthreads();

    // ---- Stage 5: m1 = relu(h_corr@mW1_top + h_prev@mW1_bot + mb1) -> tmpT ----
    GEMM_ZERO();
    gemm_slice(mW1, hcT, c, k0, acc);
    gemm_slice(mW1 + HID * HID, hvT, c, k0, acc);
    GEMM_STORE();
    __syncthreads();
    { REDUCE(x); tmpF[p] = fmaxf(x + mb1[bidx], 0.0f); }
    __syncthreads();

    // ---- Stage 6: mixed = h_corr + m1 @ mW2 + mb2 -> global ----
    GEMM_ZERO();
    gemm_slice(mW2, tmpT, c, k0, acc);
    GEMM_STORE();
    __syncthreads();
    {
        REDUCE(v);
        int cc = p >> 3, r = p & 7;   // p = cc*8 + r
        out[(r0 + r) * HID + cc] = hcv + v + mb2[cc];
    }
}

extern "C" void kernel_launch(void* const* d_in, const int* in_sizes, int n_in,
                              void* d_out, int out_size) {
    // metadata order: h_prev, h_pred, adj_rows, adj_cols, Wq, bq, Wk, bk,
    //                 Wv, bv, Wo, bo, gW1, gb1, gW2, gb2, mW1, mb1, mW2, mb2
    const float* h_prev = (const float*)d_in[0];
    const float* h_pred = (const float*)d_in[1];
    // d_in[2..7] (adjacency, Wq/bq/Wk/bk) are algebraically dead.
    const float* Wv  = (const float*)d_in[8];
    const float* bv  = (const float*)d_in[9];
    const float* Wo  = (const float*)d_in[10];
    const float* bo  = (const float*)d_in[11];
    const float* gW1 = (const float*)d_in[12];
    const float* gb1 = (const float*)d_in[13];
    const float* gW2 = (const float*)d_in[14];
    const float* gb2 = (const float*)d_in[15];
    const float* mW1 = (const float*)d_in[16];
    const float* mb1 = (const float*)d_in[17];
    const float* mW2 = (const float*)d_in[18];
    const float* mb2 = (const float*)d_in[19];
    float* out = (float*)d_out;

    temporal_attn_fused<<<NNODES / ROWS, NTHREADS>>>(
        h_prev, h_pred, Wv, bv, Wo, bo,
        gW1, gb1, gW2, gb2, mW1, mb1, mW2, mb2, out);
}